// round 2
// baseline (speedup 1.0000x reference)
#include <cuda_runtime.h>
#include <cstddef>

#define BB   2
#define TT   512
#define BT   1024      // BB*TT rows
#define NH   16
#define FD   16
#define HD   64
#define HID  1024
#define DPHI 153
#define DPAD 160
#define NG   5         // phi-dim groups of 32
#define EPSI 1e-12f

// ---- scratch (static __device__, no allocs) ----
__device__ float g_q[BT * NH * FD];            // [row][h*16+f]
__device__ float g_k[BT * NH * FD];
__device__ float g_v[BT * HID];                // [row][h*64+d]
__device__ float g_y[BT * HID];                // normalized attention out
__device__ float g_ypart[NG * BT * HID];       // per-group partial y
__device__ float g_dpart[NG * BB * NH * TT];   // per-group partial denom

// ============================================================================
// Generic NT GEMM: C[M,N] = A[M,K] @ B[N,K]^T, all row-major fp32.
// Block 64x64, BK=16, 256 threads, 4x4 per thread.
// M,N multiples of 64; K multiple of 16. (Holds for all our shapes.)
// ============================================================================
__global__ __launch_bounds__(256) void gemm_nt(
    const float* __restrict__ A, const float* __restrict__ Bw,
    float* __restrict__ C, int M, int N, int K)
{
    __shared__ float As[16][68];
    __shared__ float Bs[16][68];

    const int tid = threadIdx.x;
    const int tx = tid & 15;          // 0..15 (N micro)
    const int ty = tid >> 4;          // 0..15 (M micro)
    const int tr = tid >> 2;          // 0..63 row-in-tile for loads
    const int tc = (tid & 3) << 2;    // k offset 0,4,8,12

    const float* Ap = A  + (size_t)(blockIdx.y * 64 + tr) * K + tc;
    const float* Bp = Bw + (size_t)(blockIdx.x * 64 + tr) * K + tc;

    float acc[4][4];
#pragma unroll
    for (int i = 0; i < 4; i++)
#pragma unroll
        for (int j = 0; j < 4; j++) acc[i][j] = 0.f;

    for (int k0 = 0; k0 < K; k0 += 16) {
        float4 a4 = *(const float4*)(Ap + k0);
        float4 b4 = *(const float4*)(Bp + k0);
        As[tc + 0][tr] = a4.x; As[tc + 1][tr] = a4.y;
        As[tc + 2][tr] = a4.z; As[tc + 3][tr] = a4.w;
        Bs[tc + 0][tr] = b4.x; Bs[tc + 1][tr] = b4.y;
        Bs[tc + 2][tr] = b4.z; Bs[tc + 3][tr] = b4.w;
        __syncthreads();

#pragma unroll
        for (int kk = 0; kk < 16; kk++) {
            float4 av = *(const float4*)&As[kk][ty << 2];
            float4 bv = *(const float4*)&Bs[kk][tx << 2];
            acc[0][0] = fmaf(av.x, bv.x, acc[0][0]);
            acc[0][1] = fmaf(av.x, bv.y, acc[0][1]);
            acc[0][2] = fmaf(av.x, bv.z, acc[0][2]);
            acc[0][3] = fmaf(av.x, bv.w, acc[0][3]);
            acc[1][0] = fmaf(av.y, bv.x, acc[1][0]);
            acc[1][1] = fmaf(av.y, bv.y, acc[1][1]);
            acc[1][2] = fmaf(av.y, bv.z, acc[1][2]);
            acc[1][3] = fmaf(av.y, bv.w, acc[1][3]);
            acc[2][0] = fmaf(av.z, bv.x, acc[2][0]);
            acc[2][1] = fmaf(av.z, bv.y, acc[2][1]);
            acc[2][2] = fmaf(av.z, bv.z, acc[2][2]);
            acc[2][3] = fmaf(av.z, bv.w, acc[2][3]);
            acc[3][0] = fmaf(av.w, bv.x, acc[3][0]);
            acc[3][1] = fmaf(av.w, bv.y, acc[3][1]);
            acc[3][2] = fmaf(av.w, bv.z, acc[3][2]);
            acc[3][3] = fmaf(av.w, bv.w, acc[3][3]);
        }
        __syncthreads();
    }

    float* Cp = C + (size_t)(blockIdx.y * 64 + (ty << 2)) * N
                  + blockIdx.x * 64 + (tx << 2);
#pragma unroll
    for (int i = 0; i < 4; i++) {
        float4 o = make_float4(acc[i][0], acc[i][1], acc[i][2], acc[i][3]);
        *(float4*)(Cp + (size_t)i * N) = o;
    }
}

// ============================================================================
// Causal linear attention with Taylor feature map.
// Grid: (NG=5 phi-groups, BB*NH=32). Block: 256 threads.
// Thread: d = tid>>2 (0..63), g = tid&3; owns 8 contiguous phi slots
//         [grp*32 + g*8, +8) of the zero-padded 160-dim feature map.
// Per step: stage raw q/k/v -> compute full phi(q),phi(k) in smem ->
//           KV state update + q.KV partial dot -> shfl-reduce over g.
// Threads with d==0 additionally carry the Z (denominator) state slice.
// ============================================================================
__global__ __launch_bounds__(256) void attn_kernel()
{
    const int grp = blockIdx.x;            // 0..NG-1
    const int bh  = blockIdx.y;            // 0..31
    const int b   = bh >> 4;
    const int h   = bh & 15;
    const int tid = threadIdx.x;
    const int d   = tid >> 2;              // 0..63
    const int g   = tid & 3;               // 0..3
    const int Dbase = grp * 32 + g * 8;    // first phi index this thread owns

    __shared__ float sk[FD], sq[FD], sv[HD];
    __shared__ float sphik[DPAD], sphiq[DPAD];

    // per-thread phi-entry mapping (fixed across t)
    int typ = 0, pi = 0, pj = 0;
    if (tid == 0)            { typ = 0; }
    else if (tid < 17)       { typ = 1; pi = tid - 1; }
    else if (tid < 33)       { typ = 2; pi = tid - 17; }
    else if (tid < DPHI) {
        typ = 3;
        int pp = tid - 33, i = 0;
        while (pp >= 15 - i) { pp -= 15 - i; i++; }
        pi = i; pj = i + 1 + pp;
    }
    if (tid >= DPHI && tid < DPAD) { sphik[tid] = 0.f; sphiq[tid] = 0.f; }

    float KV[8] = {0, 0, 0, 0, 0, 0, 0, 0};
    float Z[8]  = {0, 0, 0, 0, 0, 0, 0, 0};

    const float inv_rrd  = 0.5f;                    // 1/sqrt(sqrt(16))
    const float inv_rdr2 = 0.17677669529663687f;    // 1/(4*sqrt(2))
    const float inv_rd   = 0.25f;                   // 1/4

    for (int t = 0; t < TT; t++) {
        const size_t row = (size_t)b * TT + t;
        // ---- stage raw q,k,v for this step ----
        if (tid < FD)                 sk[tid]       = g_k[row * (NH * FD) + h * FD + tid];
        else if (tid < 2 * FD)        sq[tid - FD]  = g_q[row * (NH * FD) + h * FD + (tid - FD)];
        else if (tid < 2 * FD + HD)   sv[tid - 32]  = g_v[row * HID + h * HD + (tid - 32)];
        __syncthreads();

        // ---- Taylor feature map (153 entries) ----
        if (tid < DPHI) {
            float vk, vq;
            if (typ == 0)      { vk = 1.f; vq = 1.f; }
            else if (typ == 1) { vk = sk[pi] * inv_rrd;           vq = sq[pi] * inv_rrd; }
            else if (typ == 2) { vk = sk[pi] * sk[pi] * inv_rdr2; vq = sq[pi] * sq[pi] * inv_rdr2; }
            else               { vk = sk[pi] * sk[pj] * inv_rd;   vq = sq[pi] * sq[pj] * inv_rd; }
            sphik[tid] = vk;
            sphiq[tid] = vq;
        }
        __syncthreads();

        // ---- state update + partial dots ----
        const float vd = sv[d];
        float4 pk0 = *(const float4*)&sphik[Dbase];
        float4 pk1 = *(const float4*)&sphik[Dbase + 4];
        float4 pq0 = *(const float4*)&sphiq[Dbase];
        float4 pq1 = *(const float4*)&sphiq[Dbase + 4];

        KV[0] = fmaf(pk0.x, vd, KV[0]);
        KV[1] = fmaf(pk0.y, vd, KV[1]);
        KV[2] = fmaf(pk0.z, vd, KV[2]);
        KV[3] = fmaf(pk0.w, vd, KV[3]);
        KV[4] = fmaf(pk1.x, vd, KV[4]);
        KV[5] = fmaf(pk1.y, vd, KV[5]);
        KV[6] = fmaf(pk1.z, vd, KV[6]);
        KV[7] = fmaf(pk1.w, vd, KV[7]);

        float acc;
        acc = pq0.x * KV[0];
        acc = fmaf(pq0.y, KV[1], acc);
        acc = fmaf(pq0.z, KV[2], acc);
        acc = fmaf(pq0.w, KV[3], acc);
        acc = fmaf(pq1.x, KV[4], acc);
        acc = fmaf(pq1.y, KV[5], acc);
        acc = fmaf(pq1.z, KV[6], acc);
        acc = fmaf(pq1.w, KV[7], acc);

        float dac = 0.f;
        if (d == 0) {   // 4 threads (tid 0..3) carry the Z state for this group
            Z[0] += pk0.x; Z[1] += pk0.y; Z[2] += pk0.z; Z[3] += pk0.w;
            Z[4] += pk1.x; Z[5] += pk1.y; Z[6] += pk1.z; Z[7] += pk1.w;
            dac = pq0.x * Z[0];
            dac = fmaf(pq0.y, Z[1], dac);
            dac = fmaf(pq0.z, Z[2], dac);
            dac = fmaf(pq0.w, Z[3], dac);
            dac = fmaf(pq1.x, Z[4], dac);
            dac = fmaf(pq1.y, Z[5], dac);
            dac = fmaf(pq1.z, Z[6], dac);
            dac = fmaf(pq1.w, Z[7], dac);
        }

        // reduce over the 4 g-lanes (consecutive lanes, 4-aligned groups)
        acc += __shfl_xor_sync(0xffffffffu, acc, 1);
        acc += __shfl_xor_sync(0xffffffffu, acc, 2);
        dac += __shfl_xor_sync(0xffffffffu, dac, 1);
        dac += __shfl_xor_sync(0xffffffffu, dac, 2);

        if (g == 0)
            g_ypart[((size_t)grp * BT + row) * HID + h * HD + d] = acc;
        if (tid == 0)
            g_dpart[((size_t)grp * BB * NH + bh) * TT + t] = dac;

        __syncthreads();   // protect sk/sq/sv/sphik/sphiq before next stage
    }
}

// ============================================================================
// Sum the NG group partials, divide by (denom + eps).
// ============================================================================
__global__ __launch_bounds__(256) void reduce_kernel()
{
    const int idx = blockIdx.x * blockDim.x + threadIdx.x;
    if (idx >= BT * HID) return;
    const int row = idx >> 10;        // b*TT + t
    const int col = idx & 1023;       // h*64 + d
    const int h   = col >> 6;
    const int b   = row >> 9;         // TT = 512
    const int t   = row & 511;
    const int bh  = b * NH + h;

    float s = 0.f, dn = EPSI;
#pragma unroll
    for (int gg = 0; gg < NG; gg++) {
        s  += g_ypart[((size_t)gg * BT + row) * HID + col];
        dn += g_dpart[((size_t)gg * BB * NH + bh) * TT + t];
    }
    g_y[idx] = s / dn;
}

// ============================================================================
// kernel_launch
// inputs: 0=hidden_states (2,512,1024) 1=Wq (256,1024) 2=Wk (256,1024)
//         3=Wv (1024,1024) 4=Wo (1024,1024) ; out float32 (2,512,1024)
// ============================================================================
extern "C" void kernel_launch(void* const* d_in, const int* in_sizes, int n_in,
                              void* d_out, int out_size)
{
    const float* hs = (const float*)d_in[0];
    const float* Wq = (const float*)d_in[1];
    const float* Wk = (const float*)d_in[2];
    const float* Wv = (const float*)d_in[3];
    const float* Wo = (const float*)d_in[4];
    float* out = (float*)d_out;

    float *pq, *pk, *pv, *py;
    cudaGetSymbolAddress((void**)&pq, g_q);
    cudaGetSymbolAddress((void**)&pk, g_k);
    cudaGetSymbolAddress((void**)&pv, g_v);
    cudaGetSymbolAddress((void**)&py, g_y);

    // projections
    gemm_nt<<<dim3((NH * FD) / 64, BT / 64), 256>>>(hs, Wq, pq, BT, NH * FD, HID);
    gemm_nt<<<dim3((NH * FD) / 64, BT / 64), 256>>>(hs, Wk, pk, BT, NH * FD, HID);
    gemm_nt<<<dim3(HID / 64, BT / 64), 256>>>(hs, Wv, pv, BT, HID, HID);

    // causal linear attention (phi-group split)
    attn_kernel<<<dim3(NG, BB * NH), 256>>>();

    // combine group partials + normalize
    reduce_kernel<<<(BT * HID) / 256, 256>>>();

    // output projection
    gemm_nt<<<dim3(HID / 64, BT / 64), 256>>>(py, Wo, out, BT, HID, HID);
}

// round 6
// speedup vs baseline: 1.9530x; 1.9530x over previous
#include <cuda_runtime.h>
#include <cstddef>

#define BB   2
#define TT   512
#define BT   1024      // BB*TT rows
#define NH   16
#define FD   16
#define HD   64
#define HID  1024
#define DPHI 153
#define DPAD 160
#define CHK  64        // chunk length
#define NC   8         // chunks per sequence (TT/CHK)
#define NBH  32        // BB*NH
#define NTASK (NBH*NC) // 256 chunk tasks
#define EPSI 1e-12f

// ---- scratch (static __device__, no allocs) ----
__device__ float g_q[BT * NH * FD];              // [row][h*16+f]
__device__ float g_k[BT * NH * FD];
__device__ float g_v[BT * HID];                  // [row][h*64+d]
__device__ float g_y[BT * HID];                  // normalized attention out
__device__ float g_G[NTASK * DPAD * HD];         // per-chunk  phiK^T @ V   [task][D][d]
__device__ float g_S[NTASK * DPAD * HD];         // exclusive prefix of G
__device__ float g_cs[NTASK * DPAD];             // per-chunk colsum(phiK)  [task][D]
__device__ float g_Z[NTASK * DPAD];              // exclusive prefix of cs

// phi mapping: phi[D] = sc * x[pi] * x[pj], with x[16] := 1
__device__ __forceinline__ void phi_map(int D, int& pi, int& pj, float& sc)
{
    pi = 16; pj = 16; sc = 0.f;
    if (D == 0)        { sc = 1.f; }
    else if (D < 17)   { pi = D - 1;  sc = 0.5f; }                    // x / sqrt(sqrt(16))
    else if (D < 33)   { pi = D - 17; pj = pi; sc = 0.17677669529663687f; } // x^2/(4*sqrt2)
    else if (D < DPHI) {
        int pp = D - 33, i = 0;
        while (pp >= 15 - i) { pp -= 15 - i; i++; }
        pi = i; pj = i + 1 + pp; sc = 0.25f;                          // x_i x_j / 4
    }
    // D in [153,160): sc = 0 -> zero pad
}

// ============================================================================
// Generic NT GEMM: C[M,N] = A[M,K] @ B[N,K]^T, all row-major fp32.
// Block 64x64, BK=16, 256 threads, 4x4 per thread.
// ============================================================================
__global__ __launch_bounds__(256) void gemm_nt(
    const float* __restrict__ A, const float* __restrict__ Bw,
    float* __restrict__ C, int M, int N, int K)
{
    __shared__ float As[16][68];
    __shared__ float Bs[16][68];

    const int tid = threadIdx.x;
    const int tx = tid & 15;
    const int ty = tid >> 4;
    const int tr = tid >> 2;
    const int tc = (tid & 3) << 2;

    const float* Ap = A  + (size_t)(blockIdx.y * 64 + tr) * K + tc;
    const float* Bp = Bw + (size_t)(blockIdx.x * 64 + tr) * K + tc;

    float acc[4][4];
#pragma unroll
    for (int i = 0; i < 4; i++)
#pragma unroll
        for (int j = 0; j < 4; j++) acc[i][j] = 0.f;

    for (int k0 = 0; k0 < K; k0 += 16) {
        float4 a4 = *(const float4*)(Ap + k0);
        float4 b4 = *(const float4*)(Bp + k0);
        As[tc + 0][tr] = a4.x; As[tc + 1][tr] = a4.y;
        As[tc + 2][tr] = a4.z; As[tc + 3][tr] = a4.w;
        Bs[tc + 0][tr] = b4.x; Bs[tc + 1][tr] = b4.y;
        Bs[tc + 2][tr] = b4.z; Bs[tc + 3][tr] = b4.w;
        __syncthreads();

#pragma unroll
        for (int kk = 0; kk < 16; kk++) {
            float4 av = *(const float4*)&As[kk][ty << 2];
            float4 bv = *(const float4*)&Bs[kk][tx << 2];
            acc[0][0] = fmaf(av.x, bv.x, acc[0][0]);
            acc[0][1] = fmaf(av.x, bv.y, acc[0][1]);
            acc[0][2] = fmaf(av.x, bv.z, acc[0][2]);
            acc[0][3] = fmaf(av.x, bv.w, acc[0][3]);
            acc[1][0] = fmaf(av.y, bv.x, acc[1][0]);
            acc[1][1] = fmaf(av.y, bv.y, acc[1][1]);
            acc[1][2] = fmaf(av.y, bv.z, acc[1][2]);
            acc[1][3] = fmaf(av.y, bv.w, acc[1][3]);
            acc[2][0] = fmaf(av.z, bv.x, acc[2][0]);
            acc[2][1] = fmaf(av.z, bv.y, acc[2][1]);
            acc[2][2] = fmaf(av.z, bv.z, acc[2][2]);
            acc[2][3] = fmaf(av.z, bv.w, acc[2][3]);
            acc[3][0] = fmaf(av.w, bv.x, acc[3][0]);
            acc[3][1] = fmaf(av.w, bv.y, acc[3][1]);
            acc[3][2] = fmaf(av.w, bv.z, acc[3][2]);
            acc[3][3] = fmaf(av.w, bv.w, acc[3][3]);
        }
        __syncthreads();
    }

    float* Cp = C + (size_t)(blockIdx.y * 64 + (ty << 2)) * N
                  + blockIdx.x * 64 + (tx << 2);
#pragma unroll
    for (int i = 0; i < 4; i++) {
        float4 o = make_float4(acc[i][0], acc[i][1], acc[i][2], acc[i][3]);
        *(float4*)(Cp + (size_t)i * N) = o;
    }
}

// ============================================================================
// Kernel A: per chunk, G = phiK^T @ V  (DPAD x HD) and colsum(phiK) (DPAD).
// One block per (bh, chunk). 256 threads: ty(16) x 10 D-rows, tx(16) x 4 d.
// ============================================================================
struct SmemA {
    float P[DPAD][68];   // phiK transposed: [D][t]
    float V[CHK][68];    // [t][d]
    float R[CHK][17];    // raw k, col 16 = 1
};

__global__ __launch_bounds__(256) void chunk_outer()
{
    extern __shared__ float sm_raw[];
    SmemA* s = (SmemA*)sm_raw;
    const int task = blockIdx.x;
    const int bh = task >> 3, c = task & 7;
    const int b = bh >> 4, h = bh & 15, t0 = c * CHK;
    const int tid = threadIdx.x;

    for (int e = tid; e < CHK * FD; e += 256) {
        int t = e >> 4, f = e & 15;
        s->R[t][f] = g_k[((size_t)(b * TT + t0 + t)) * (NH * FD) + h * FD + f];
    }
    if (tid < CHK) s->R[tid][16] = 1.f;
    for (int e = tid; e < CHK * 16; e += 256) {
        int t = e >> 4, d4 = (e & 15) << 2;
        *(float4*)&s->V[t][d4] =
            *(const float4*)&g_v[((size_t)(b * TT + t0 + t)) * HID + h * HD + d4];
    }
    __syncthreads();

    if (tid < DPAD) {
        int pi, pj; float sc;
        phi_map(tid, pi, pj, sc);
#pragma unroll 4
        for (int t = 0; t < CHK; t++)
            s->P[tid][t] = sc * s->R[t][pi] * s->R[t][pj];
    }
    __syncthreads();

    const int tx = tid & 15, ty = tid >> 4;
    float acc[10][4];
#pragma unroll
    for (int r = 0; r < 10; r++)
#pragma unroll
        for (int j = 0; j < 4; j++) acc[r][j] = 0.f;

    for (int t = 0; t < CHK; t++) {
        float4 v4 = *(float4*)&s->V[t][tx << 2];
#pragma unroll
        for (int r = 0; r < 10; r++) {
            float p = s->P[ty * 10 + r][t];
            acc[r][0] = fmaf(p, v4.x, acc[r][0]);
            acc[r][1] = fmaf(p, v4.y, acc[r][1]);
            acc[r][2] = fmaf(p, v4.z, acc[r][2]);
            acc[r][3] = fmaf(p, v4.w, acc[r][3]);
        }
    }

    float* Gp = g_G + (size_t)task * (DPAD * HD);
#pragma unroll
    for (int r = 0; r < 10; r++)
        *(float4*)&Gp[(ty * 10 + r) * HD + (tx << 2)] =
            make_float4(acc[r][0], acc[r][1], acc[r][2], acc[r][3]);

    // column sums of phiK
    if (tid < DPAD) {
        float cs = 0.f;
#pragma unroll 4
        for (int t = 0; t < CHK; t++) cs += s->P[tid][t];
        g_cs[(size_t)task * DPAD + tid] = cs;
    }
}

// ============================================================================
// Kernel B: exclusive prefix over chunks: S_c = sum_{c'<c} G_{c'}; Z likewise.
// One block per bh.
// ============================================================================
__global__ __launch_bounds__(256) void prefix_kernel()
{
    const int bh = blockIdx.x;
    const int tid = threadIdx.x;
    const size_t base = (size_t)bh * NC;

    for (int e = tid; e < DPAD * HD; e += 256) {
        float carry = 0.f;
#pragma unroll
        for (int c = 0; c < NC; c++) {
            size_t idx = (base + c) * (DPAD * HD) + e;
            float v = g_G[idx];
            g_S[idx] = carry;
            carry += v;
        }
    }
    for (int e = tid; e < DPAD; e += 256) {
        float carry = 0.f;
#pragma unroll
        for (int c = 0; c < NC; c++) {
            size_t idx = (base + c) * DPAD + e;
            float v = g_cs[idx];
            g_Z[idx] = carry;
            carry += v;
        }
    }
}

// ============================================================================
// Kernel C: per chunk task:
//   A = phiQ @ phiK^T (64x64), masked causal;
//   y = tril(A) @ V + phiQ @ S;  denom = rowsum(tril(A)) + phiQ . Z
//   write y/(denom+eps) directly to g_y.
// 256 threads: ty(16) x 4 t-rows, tx(16) x 4 d-cols.
// ============================================================================
struct SmemC {
    float Q[DPAD][68];   // phiQ^T: [D][t]
    float K[DPAD][68];   // phiK^T: [D][t]
    float A[CHK][68];    // masked A [t][t']
    float V[CHK][68];    // [t'][d]
    float RQ[CHK][17];
    float RK[CHK][17];
    float Den[CHK];      // intra denom
    float Di[CHK];       // inter denom
};

__global__ __launch_bounds__(256) void attn_chunk()
{
    extern __shared__ float sm_raw[];
    SmemC* s = (SmemC*)sm_raw;
    const int task = blockIdx.x;
    const int bh = task >> 3, c = task & 7;
    const int b = bh >> 4, h = bh & 15, t0 = c * CHK;
    const int tid = threadIdx.x;

    for (int e = tid; e < CHK * FD; e += 256) {
        int t = e >> 4, f = e & 15;
        size_t row = (size_t)(b * TT + t0 + t);
        s->RQ[t][f] = g_q[row * (NH * FD) + h * FD + f];
        s->RK[t][f] = g_k[row * (NH * FD) + h * FD + f];
    }
    if (tid < CHK) { s->RQ[tid][16] = 1.f; s->RK[tid][16] = 1.f; }
    for (int e = tid; e < CHK * 16; e += 256) {
        int t = e >> 4, d4 = (e & 15) << 2;
        *(float4*)&s->V[t][d4] =
            *(const float4*)&g_v[((size_t)(b * TT + t0 + t)) * HID + h * HD + d4];
    }
    __syncthreads();

    if (tid < DPAD) {
        int pi, pj; float sc;
        phi_map(tid, pi, pj, sc);
#pragma unroll 4
        for (int t = 0; t < CHK; t++) {
            s->Q[tid][t] = sc * s->RQ[t][pi] * s->RQ[t][pj];
            s->K[tid][t] = sc * s->RK[t][pi] * s->RK[t][pj];
        }
    }
    __syncthreads();

    const int tx = tid & 15, ty = tid >> 4;

    // ---- phase 1: A = phiQ @ phiK^T ----
    float a[4][4];
#pragma unroll
    for (int i = 0; i < 4; i++)
#pragma unroll
        for (int j = 0; j < 4; j++) a[i][j] = 0.f;

#pragma unroll 4
    for (int k = 0; k < DPAD; k++) {
        float4 qa = *(float4*)&s->Q[k][ty << 2];
        float4 kb = *(float4*)&s->K[k][tx << 2];
        a[0][0] = fmaf(qa.x, kb.x, a[0][0]);
        a[0][1] = fmaf(qa.x, kb.y, a[0][1]);
        a[0][2] = fmaf(qa.x, kb.z, a[0][2]);
        a[0][3] = fmaf(qa.x, kb.w, a[0][3]);
        a[1][0] = fmaf(qa.y, kb.x, a[1][0]);
        a[1][1] = fmaf(qa.y, kb.y, a[1][1]);
        a[1][2] = fmaf(qa.y, kb.z, a[1][2]);
        a[1][3] = fmaf(qa.y, kb.w, a[1][3]);
        a[2][0] = fmaf(qa.z, kb.x, a[2][0]);
        a[2][1] = fmaf(qa.z, kb.y, a[2][1]);
        a[2][2] = fmaf(qa.z, kb.z, a[2][2]);
        a[2][3] = fmaf(qa.z, kb.w, a[2][3]);
        a[3][0] = fmaf(qa.w, kb.x, a[3][0]);
        a[3][1] = fmaf(qa.w, kb.y, a[3][1]);
        a[3][2] = fmaf(qa.w, kb.z, a[3][2]);
        a[3][3] = fmaf(qa.w, kb.w, a[3][3]);
    }

    // ---- mask + store A + intra denom rowsums ----
    float p[4] = {0.f, 0.f, 0.f, 0.f};
#pragma unroll
    for (int i = 0; i < 4; i++) {
        int trow = (ty << 2) + i;
        float4 m;
        m.x = ((tx << 2) + 0 <= trow) ? a[i][0] : 0.f;
        m.y = ((tx << 2) + 1 <= trow) ? a[i][1] : 0.f;
        m.z = ((tx << 2) + 2 <= trow) ? a[i][2] : 0.f;
        m.w = ((tx << 2) + 3 <= trow) ? a[i][3] : 0.f;
        *(float4*)&s->A[trow][tx << 2] = m;
        p[i] = m.x + m.y + m.z + m.w;
    }
#pragma unroll
    for (int i = 0; i < 4; i++) {
        p[i] += __shfl_xor_sync(0xffffffffu, p[i], 1);
        p[i] += __shfl_xor_sync(0xffffffffu, p[i], 2);
        p[i] += __shfl_xor_sync(0xffffffffu, p[i], 4);
        p[i] += __shfl_xor_sync(0xffffffffu, p[i], 8);
    }
    if (tx == 0) {
#pragma unroll
        for (int i = 0; i < 4; i++) s->Den[(ty << 2) + i] = p[i];
    }

    // ---- inter denom: phiQ_t . Z ----
    if (tid < CHK) {
        const float* Zp = g_Z + (size_t)task * DPAD;
        float di = 0.f;
#pragma unroll 4
        for (int k = 0; k < DPAD; k++)
            di = fmaf(s->Q[k][tid], __ldg(&Zp[k]), di);
        s->Di[tid] = di;
    }
    __syncthreads();

    // ---- phase 2: y = tril(A) @ V + phiQ @ S ----
    float y[4][4];
#pragma unroll
    for (int i = 0; i < 4; i++)
#pragma unroll
        for (int j = 0; j < 4; j++) y[i][j] = 0.f;

#pragma unroll 4
    for (int k = 0; k < CHK; k++) {
        float4 v4 = *(float4*)&s->V[k][tx << 2];
        float a0 = s->A[(ty << 2) + 0][k];
        float a1 = s->A[(ty << 2) + 1][k];
        float a2 = s->A[(ty << 2) + 2][k];
        float a3 = s->A[(ty << 2) + 3][k];
        y[0][0] = fmaf(a0, v4.x, y[0][0]); y[0][1] = fmaf(a0, v4.y, y[0][1]);
        y[0][2] = fmaf(a0, v4.z, y[0][2]); y[0][3] = fmaf(a0, v4.w, y[0][3]);
        y[1][0] = fmaf(a1, v4.x, y[1][0]); y[1][1] = fmaf(a1, v4.y, y[1][1]);
        y[1][2] = fmaf(a1, v4.z, y[1][2]); y[1][3] = fmaf(a1, v4.w, y[1][3]);
        y[2][0] = fmaf(a2, v4.x, y[2][0]); y[2][1] = fmaf(a2, v4.y, y[2][1]);
        y[2][2] = fmaf(a2, v4.z, y[2][2]); y[2][3] = fmaf(a2, v4.w, y[2][3]);
        y[3][0] = fmaf(a3, v4.x, y[3][0]); y[3][1] = fmaf(a3, v4.y, y[3][1]);
        y[3][2] = fmaf(a3, v4.z, y[3][2]); y[3][3] = fmaf(a3, v4.w, y[3][3]);
    }

    const float* Sp = g_S + (size_t)task * (DPAD * HD);
#pragma unroll 4
    for (int k = 0; k < DPAD; k++) {
        float4 s4 = __ldg((const float4*)&Sp[k * HD + (tx << 2)]);
        float4 q4 = *(float4*)&s->Q[k][ty << 2];
        y[0][0] = fmaf(q4.x, s4.x, y[0][0]); y[0][1] = fmaf(q4.x, s4.y, y[0][1]);
        y[0][2] = fmaf(q4.x, s4.z, y[0][2]); y[0][3] = fmaf(q4.x, s4.w, y[0][3]);
        y[1][0] = fmaf(q4.y, s4.x, y[1][0]); y[1][1] = fmaf(q4.y, s4.y, y[1][1]);
        y[1][2] = fmaf(q4.y, s4.z, y[1][2]); y[1][3] = fmaf(q4.y, s4.w, y[1][3]);
        y[2][0] = fmaf(q4.z, s4.x, y[2][0]); y[2][1] = fmaf(q4.z, s4.y, y[2][1]);
        y[2][2] = fmaf(q4.z, s4.z, y[2][2]); y[2][3] = fmaf(q4.z, s4.w, y[2][3]);
        y[3][0] = fmaf(q4.w, s4.x, y[3][0]); y[3][1] = fmaf(q4.w, s4.y, y[3][1]);
        y[3][2] = fmaf(q4.w, s4.z, y[3][2]); y[3][3] = fmaf(q4.w, s4.w, y[3][3]);
    }

    // ---- normalize + write ----
#pragma unroll
    for (int i = 0; i < 4; i++) {
        int trow = (ty << 2) + i;
        float dn = 1.f / (s->Den[trow] + s->Di[trow] + EPSI);
        float4 o = make_float4(y[i][0] * dn, y[i][1] * dn, y[i][2] * dn, y[i][3] * dn);
        *(float4*)&g_y[((size_t)(b * TT + t0 + trow)) * HID + h * HD + (tx << 2)] = o;
    }
}

// ============================================================================
// kernel_launch
// ============================================================================
extern "C" void kernel_launch(void* const* d_in, const int* in_sizes, int n_in,
                              void* d_out, int out_size)
{
    const float* hs = (const float*)d_in[0];
    const float* Wq = (const float*)d_in[1];
    const float* Wk = (const float*)d_in[2];
    const float* Wv = (const float*)d_in[3];
    const float* Wo = (const float*)d_in[4];
    float* out = (float*)d_out;

    float *pq, *pk, *pv, *py;
    cudaGetSymbolAddress((void**)&pq, g_q);
    cudaGetSymbolAddress((void**)&pk, g_k);
    cudaGetSymbolAddress((void**)&pv, g_v);
    cudaGetSymbolAddress((void**)&py, g_y);

    const int smemA = (int)sizeof(SmemA);
    const int smemC = (int)sizeof(SmemC);
    cudaFuncSetAttribute(chunk_outer, cudaFuncAttributeMaxDynamicSharedMemorySize, smemA);
    cudaFuncSetAttribute(attn_chunk,  cudaFuncAttributeMaxDynamicSharedMemorySize, smemC);

    // projections
    gemm_nt<<<dim3((NH * FD) / 64, BT / 64), 256>>>(hs, Wq, pq, BT, NH * FD, HID);
    gemm_nt<<<dim3((NH * FD) / 64, BT / 64), 256>>>(hs, Wk, pk, BT, NH * FD, HID);
    gemm_nt<<<dim3(HID / 64, BT / 64), 256>>>(hs, Wv, pv, BT, HID, HID);

    // chunked causal linear attention
    chunk_outer<<<NTASK, 256, smemA>>>();
    prefix_kernel<<<NBH, 256>>>();
    attn_chunk<<<NTASK, 256, smemC>>>();

    // output projection
    gemm_nt<<<dim3(HID / 64, BT / 64), 256>>>(py, Wo, out, BT, HID, HID);
}